// round 1
// baseline (speedup 1.0000x reference)
#include <cuda_runtime.h>
#include <math.h>

#define NREG 36
#define EMBD 1024
#define SIMD 16
#define HIDD 32
#define NKER 8

struct Smem {
    float A[NREG * EMBD];      // inp1 tile (fp32)
    float G[NREG * NREG];      // gram -> distances (in-place)
    float sv[NREG * SIMD];     // sim_vec
    float gw[NKER * SIMD * HIDD];
    float w1n[HIDD * 33];      // weight-normed out1 (padded rows)
    float w2n[HIDD];
    float b1h[HIDD];
    float mk[NKER];
    float pk[NKER];
    float b2s;
    float invn[NREG];
    float nf[NKER * NREG];     // S/(S+eps)
    float hid[NREG * HIDD];
    float h1[NREG * 33];       // padded
    float sarr[NREG];
};

// Fast exp on the FMA pipe (avoid MUFU: 21M exps would be MUFU-bound otherwise).
// exp(x) = 2^(x*log2e); degree-5 poly for 2^f, f in [-0.5,0.5]; rel err ~2.4e-6.
__device__ __forceinline__ float fexp(float x) {
    float y = x * 1.4426950408889634f;
    y = fmaxf(y, -126.0f);
    float r = rintf(y);
    float f = y - r;
    float p = 1.3333557100e-3f;
    p = fmaf(p, f, 9.6181291076e-3f);
    p = fmaf(p, f, 5.5504108665e-2f);
    p = fmaf(p, f, 2.4022650696e-1f);
    p = fmaf(p, f, 6.9314718056e-1f);
    p = fmaf(p, f, 1.0f);
    int ei = (int)r;
    float s = __int_as_float((ei + 127) << 23);
    return p * s;
}

__global__ void __launch_bounds__(512, 1)
simgsmn_kernel(const float* __restrict__ inp1, const float* __restrict__ inp2,
               const float* __restrict__ gk_mean, const float* __restrict__ gk_prec,
               const float* __restrict__ gcn_w, const float* __restrict__ out1_v,
               const float* __restrict__ out1_g, const float* __restrict__ out1_b,
               const float* __restrict__ out2_v, const float* __restrict__ out2_g,
               const float* __restrict__ out2_b, float* __restrict__ out)
{
    extern __shared__ char smem_raw[];
    Smem* s = reinterpret_cast<Smem*>(smem_raw);
    const int tid  = threadIdx.x;
    const int w    = tid >> 5;
    const int lane = tid & 31;
    const int b    = blockIdx.x;

    // ---- small constant prep (weight-norm, kernels, gcn weights) ----
    for (int i = tid; i < NKER * SIMD * HIDD; i += 512) s->gw[i] = gcn_w[i];
    if (tid < HIDD) {
        const int hh = tid;
        float ss = 0.f;
        #pragma unroll
        for (int h = 0; h < HIDD; h++) { float v = out1_v[hh * HIDD + h]; ss += v * v; }
        const float sc = out1_g[hh] / (sqrtf(ss) + 1e-12f);
        #pragma unroll
        for (int h = 0; h < HIDD; h++) s->w1n[hh * 33 + h] = out1_v[hh * HIDD + h] * sc;
        s->b1h[hh] = out1_b[hh];
    } else if (tid == 32) {
        float ss = 0.f;
        #pragma unroll
        for (int h = 0; h < HIDD; h++) { float v = out2_v[h]; ss += v * v; }
        const float sc = out2_g[0] / (sqrtf(ss) + 1e-12f);
        #pragma unroll
        for (int h = 0; h < HIDD; h++) s->w2n[h] = out2_v[h] * sc;
        s->b2s = out2_b[0];
    } else if (tid >= 64 && tid < 64 + NKER) {
        s->mk[tid - 64] = gk_mean[tid - 64];
        s->pk[tid - 64] = gk_prec[tid - 64];
    }

    // ---- phase 1: stream inp1/inp2, stash inp1 in smem, compute sim_vec ----
    // One warp per row; lane handles float4 index r*32+lane (fully coalesced 512B).
    // float4 f = r*32+lane covers sim-block sb = 2r + (lane>>4); reduce within 16-lane halves.
    const float4* in1 = reinterpret_cast<const float4*>(inp1) + (size_t)b * (NREG * EMBD / 4);
    const float4* in2 = reinterpret_cast<const float4*>(inp2) + (size_t)b * (NREG * EMBD / 4);
    float4* A4 = reinterpret_cast<float4*>(s->A);
    for (int i = w; i < NREG; i += 16) {
        float qq[8], cc[8], qc[8];
        #pragma unroll
        for (int r = 0; r < 8; r++) {
            float4 a = in1[i * 256 + r * 32 + lane];
            float4 c = in2[i * 256 + r * 32 + lane];
            A4[i * 256 + r * 32 + lane] = a;
            qq[r] = a.x * a.x + a.y * a.y + a.z * a.z + a.w * a.w;
            cc[r] = c.x * c.x + c.y * c.y + c.z * c.z + c.w * c.w;
            qc[r] = a.x * c.x + a.y * c.y + a.z * c.z + a.w * c.w;
        }
        #pragma unroll
        for (int r = 0; r < 8; r++) {
            float q = qq[r], c = cc[r], x = qc[r];
            #pragma unroll
            for (int d = 1; d < 16; d <<= 1) {
                q += __shfl_xor_sync(0xffffffffu, q, d);
                c += __shfl_xor_sync(0xffffffffu, c, d);
                x += __shfl_xor_sync(0xffffffffu, x, d);
            }
            if ((lane & 15) == 0) {
                const int sb = r * 2 + (lane >> 4);
                s->sv[i * SIMD + sb] = x / ((sqrtf(q) + 1e-8f) * (sqrtf(c) + 1e-8f));
            }
        }
    }
    __syncthreads();

    // ---- phase 2: gram G = A·A^T over upper-triangle 6x6 group tiles ----
    for (int t = w; t < 21; t += 16) {
        int gi = 0, rem = t;
        while (rem >= 6 - gi) { rem -= 6 - gi; gi++; }
        const int gj = gi + rem;
        float acc[36];
        #pragma unroll
        for (int q = 0; q < 36; q++) acc[q] = 0.f;
        const int baseA = gi * 6 * 256 + lane;
        const int baseB = gj * 6 * 256 + lane;
        #pragma unroll
        for (int st = 0; st < 8; st++) {
            float4 av[6], bv[6];
            #pragma unroll
            for (int a = 0; a < 6; a++) av[a] = A4[baseA + a * 256 + st * 32];
            #pragma unroll
            for (int bb = 0; bb < 6; bb++) bv[bb] = A4[baseB + bb * 256 + st * 32];
            #pragma unroll
            for (int a = 0; a < 6; a++) {
                #pragma unroll
                for (int bb = 0; bb < 6; bb++) {
                    float4 x = av[a], y = bv[bb];
                    acc[a * 6 + bb] += x.x * y.x + x.y * y.y + x.z * y.z + x.w * y.w;
                }
            }
        }
        #pragma unroll
        for (int q = 0; q < 36; q++) {
            float v = acc[q];
            v += __shfl_xor_sync(0xffffffffu, v, 16);
            v += __shfl_xor_sync(0xffffffffu, v, 8);
            v += __shfl_xor_sync(0xffffffffu, v, 4);
            v += __shfl_xor_sync(0xffffffffu, v, 2);
            v += __shfl_xor_sync(0xffffffffu, v, 1);
            if (lane == 0) {
                const int ii = gi * 6 + q / 6, jj = gj * 6 + q % 6;
                s->G[ii * 36 + jj] = v;
                if (gi != gj) s->G[jj * 36 + ii] = v;
            }
        }
    }
    __syncthreads();

    // ---- phase 3: distances + gaussian-kernel row sums ----
    if (tid < NREG) s->invn[tid] = 1.0f / (sqrtf(s->G[tid * 36 + tid]) + 1e-8f);
    __syncthreads();
    for (int p = tid; p < NREG * NREG; p += 512) {
        const int i = p / 36, j = p - i * 36;
        const float e  = s->G[p] * s->invn[i] * s->invn[j];
        const float d2 = fmaxf(2.0f - 2.0f * e, 0.0f);
        s->G[p] = sqrtf(d2 + 1e-12f);
    }
    __syncthreads();
    if (tid < NKER * NREG) {
        const int k = tid / 36, i = tid - k * 36;
        const float m = s->mk[k], pr = s->pk[k];
        float acc = 0.f;
        #pragma unroll 6
        for (int j = 0; j < 36; j++) {
            const float t2 = s->G[i * 36 + j] - m;
            acc += fexp(-0.5f * pr * t2 * t2);
        }
        s->nf[tid] = acc / (acc + 1e-8f);
    }
    __syncthreads();

    // ---- phase 4: hidden[i,h] = sum_{k,d} nf[k,i]*sv[i,d]*gw[k,d,h] ----
    for (int p = tid; p < NREG * HIDD; p += 512) {
        const int i = p >> 5, h = p & 31;
        float svv[SIMD];
        #pragma unroll
        for (int d = 0; d < SIMD; d++) svv[d] = s->sv[i * SIMD + d];
        float acc = 0.f;
        #pragma unroll
        for (int k = 0; k < NKER; k++) {
            const float c = s->nf[k * 36 + i];
            #pragma unroll
            for (int d = 0; d < SIMD; d++)
                acc = fmaf(c * svv[d], s->gw[(k * SIMD + d) * HIDD + h], acc);
        }
        s->hid[p] = acc;
    }
    __syncthreads();

    // ---- phase 5: weight-normed MLP + per-batch mean ----
    for (int p = tid; p < NREG * HIDD; p += 512) {
        const int i = p >> 5, hh = p & 31;
        float acc = s->b1h[hh];
        #pragma unroll
        for (int h = 0; h < HIDD; h++)
            acc = fmaf(s->hid[i * HIDD + h], s->w1n[hh * 33 + h], acc);
        s->h1[i * 33 + hh] = tanhf(acc);
    }
    __syncthreads();
    if (tid < NREG) {
        float acc = s->b2s;
        #pragma unroll
        for (int h = 0; h < HIDD; h++)
            acc = fmaf(s->h1[tid * 33 + h], s->w2n[h], acc);
        s->sarr[tid] = acc;
    }
    __syncthreads();
    if (tid == 0) {
        float acc = 0.f;
        #pragma unroll
        for (int i = 0; i < NREG; i++) acc += s->sarr[i];
        out[b] = acc * (1.0f / 36.0f);
    }
}

extern "C" void kernel_launch(void* const* d_in, const int* in_sizes, int n_in,
                              void* d_out, int out_size) {
    const int Bn = in_sizes[0] / (NREG * EMBD);
    cudaFuncSetAttribute(simgsmn_kernel, cudaFuncAttributeMaxDynamicSharedMemorySize,
                         (int)sizeof(Smem));
    simgsmn_kernel<<<Bn, 512, sizeof(Smem)>>>(
        (const float*)d_in[0], (const float*)d_in[1], (const float*)d_in[2],
        (const float*)d_in[3], (const float*)d_in[4], (const float*)d_in[5],
        (const float*)d_in[6], (const float*)d_in[7], (const float*)d_in[8],
        (const float*)d_in[9], (const float*)d_in[10], (float*)d_out);
}

// round 2
// speedup vs baseline: 1.9018x; 1.9018x over previous
#include <cuda_runtime.h>
#include <cuda_bf16.h>
#include <math.h>

#define NREG 36
#define EMBD 1024
#define SIMD 16
#define HIDD 32
#define NKER 8
#define AW   516   // words (uint32/bf16x2) per row: 1032 bf16 elems (2064 B, conflict-free for ldmatrix)

struct Smem {
    unsigned int A2[NREG * AW];   // bf16 inp1 tile (padded rows) -> later overlaid by hid/h1
    float G[NREG * NREG];         // gram -> distances (in-place)
    float sv[NREG * SIMD];
    float gw[NKER * SIMD * HIDD];
    float w1n[HIDD * 33];
    float w2n[HIDD];
    float b1h[HIDD];
    float mk[NKER];
    float pk[NKER];
    float invn[NREG];
    float nf[NKER * NREG];
    float sarr[NREG];
    float b2s;
};

__device__ __forceinline__ void ldsm_x4(unsigned& r0, unsigned& r1, unsigned& r2, unsigned& r3, unsigned addr) {
    asm volatile("ldmatrix.sync.aligned.m8n8.x4.shared.b16 {%0,%1,%2,%3}, [%4];"
                 : "=r"(r0), "=r"(r1), "=r"(r2), "=r"(r3) : "r"(addr));
}
__device__ __forceinline__ void ldsm_x2(unsigned& r0, unsigned& r1, unsigned addr) {
    asm volatile("ldmatrix.sync.aligned.m8n8.x2.shared.b16 {%0,%1}, [%2];"
                 : "=r"(r0), "=r"(r1) : "r"(addr));
}
__device__ __forceinline__ void mma_bf16(float c[4], unsigned a0, unsigned a1, unsigned a2, unsigned a3,
                                         unsigned b0, unsigned b1) {
    asm volatile("mma.sync.aligned.m16n8k16.row.col.f32.bf16.bf16.f32 "
                 "{%0,%1,%2,%3}, {%4,%5,%6,%7}, {%8,%9}, {%0,%1,%2,%3};"
                 : "+f"(c[0]), "+f"(c[1]), "+f"(c[2]), "+f"(c[3])
                 : "r"(a0), "r"(a1), "r"(a2), "r"(a3), "r"(b0), "r"(b1));
}

// Fast exp on the FMA pipe (MUFU would bottleneck 21M exps).
__device__ __forceinline__ float fexp(float x) {
    float y = x * 1.4426950408889634f;
    y = fmaxf(y, -126.0f);
    float r = rintf(y);
    float f = y - r;
    float p = 1.3333557100e-3f;
    p = fmaf(p, f, 9.6181291076e-3f);
    p = fmaf(p, f, 5.5504108665e-2f);
    p = fmaf(p, f, 2.4022650696e-1f);
    p = fmaf(p, f, 6.9314718056e-1f);
    p = fmaf(p, f, 1.0f);
    return p * __int_as_float(((int)r + 127) << 23);
}

__global__ void __launch_bounds__(512, 2)
simgsmn_kernel(const float* __restrict__ inp1, const float* __restrict__ inp2,
               const float* __restrict__ gk_mean, const float* __restrict__ gk_prec,
               const float* __restrict__ gcn_w, const float* __restrict__ out1_v,
               const float* __restrict__ out1_g, const float* __restrict__ out1_b,
               const float* __restrict__ out2_v, const float* __restrict__ out2_g,
               const float* __restrict__ out2_b, float* __restrict__ out)
{
    extern __shared__ char smem_raw[];
    Smem* s = reinterpret_cast<Smem*>(smem_raw);
    const int tid  = threadIdx.x;
    const int w    = tid >> 5;
    const int lane = tid & 31;
    const int b    = blockIdx.x;

    // ---- constant prep ----
    for (int i = tid; i < NKER * SIMD * HIDD; i += 512) s->gw[i] = gcn_w[i];
    if (tid < HIDD) {
        const int hh = tid;
        float ss = 0.f;
        #pragma unroll
        for (int h = 0; h < HIDD; h++) { float v = out1_v[hh * HIDD + h]; ss += v * v; }
        const float sc = out1_g[hh] / (sqrtf(ss) + 1e-12f);
        #pragma unroll
        for (int h = 0; h < HIDD; h++) s->w1n[hh * 33 + h] = out1_v[hh * HIDD + h] * sc;
        s->b1h[hh] = out1_b[hh];
    } else if (tid == 32) {
        float ss = 0.f;
        #pragma unroll
        for (int h = 0; h < HIDD; h++) { float v = out2_v[h]; ss += v * v; }
        const float sc = out2_g[0] / (sqrtf(ss) + 1e-12f);
        #pragma unroll
        for (int h = 0; h < HIDD; h++) s->w2n[h] = out2_v[h] * sc;
        s->b2s = out2_b[0];
    } else if (tid >= 64 && tid < 64 + NKER) {
        s->mk[tid - 64] = gk_mean[tid - 64];
        s->pk[tid - 64] = gk_prec[tid - 64];
    }

    // ---- phase 1: stream inp1/inp2, stash inp1 as bf16, compute sim_vec ----
    const float4* in1 = reinterpret_cast<const float4*>(inp1) + (size_t)b * (NREG * EMBD / 4);
    const float4* in2 = reinterpret_cast<const float4*>(inp2) + (size_t)b * (NREG * EMBD / 4);
    for (int i = w; i < NREG; i += 16) {
        #pragma unroll
        for (int half = 0; half < 2; half++) {
            float4 av[4], cv[4];
            #pragma unroll
            for (int r = 0; r < 4; r++) {
                const int f4 = (half * 4 + r) * 32 + lane;
                av[r] = in1[i * 256 + f4];
                cv[r] = in2[i * 256 + f4];
            }
            #pragma unroll
            for (int r = 0; r < 4; r++) {
                const int f4 = (half * 4 + r) * 32 + lane;
                __nv_bfloat162 p0 = __floats2bfloat162_rn(av[r].x, av[r].y);
                __nv_bfloat162 p1 = __floats2bfloat162_rn(av[r].z, av[r].w);
                uint2 pk;
                pk.x = *reinterpret_cast<unsigned*>(&p0);
                pk.y = *reinterpret_cast<unsigned*>(&p1);
                *reinterpret_cast<uint2*>(&s->A2[i * AW + 2 * f4]) = pk;
                float q = av[r].x * av[r].x + av[r].y * av[r].y + av[r].z * av[r].z + av[r].w * av[r].w;
                float c = cv[r].x * cv[r].x + cv[r].y * cv[r].y + cv[r].z * cv[r].z + cv[r].w * cv[r].w;
                float x = av[r].x * cv[r].x + av[r].y * cv[r].y + av[r].z * cv[r].z + av[r].w * cv[r].w;
                #pragma unroll
                for (int d = 1; d < 16; d <<= 1) {
                    q += __shfl_xor_sync(0xffffffffu, q, d);
                    c += __shfl_xor_sync(0xffffffffu, c, d);
                    x += __shfl_xor_sync(0xffffffffu, x, d);
                }
                if ((lane & 15) == 0) {
                    const int sb = (half * 4 + r) * 2 + (lane >> 4);
                    s->sv[i * SIMD + sb] = x / ((sqrtf(q) + 1e-8f) * (sqrtf(c) + 1e-8f));
                }
            }
        }
    }
    __syncthreads();

    // ---- phase 2: gram via HMMA bf16. 3 m-blocks x 5 n-blocks = 15 warp-tiles ----
    // m-blocks rows: {0-15, 16-31, 20-35}; n-blocks cols: {0-7,8-15,16-23,24-31,28-35}
    if (w < 15) {
        const int mb = w / 5, nb = w % 5;
        const int r0 = (mb == 2) ? 20 : mb * 16;
        const int n0 = (nb == 4) ? 28 : nb * 8;
        const unsigned Abase = (unsigned)__cvta_generic_to_shared(s->A2);
        unsigned a_addr = Abase + ((r0 + (lane & 15)) * 1032 + ((lane >> 4) << 3)) * 2;
        unsigned b_addr = Abase + ((n0 + (lane & 7)) * 1032 + (((lane >> 3) & 1) << 3)) * 2;
        float c0[4] = {0.f, 0.f, 0.f, 0.f}, c1[4] = {0.f, 0.f, 0.f, 0.f};
        #pragma unroll 4
        for (int kk = 0; kk < 32; kk++) {
            unsigned a0, a1, a2, a3, b0, b1;
            ldsm_x4(a0, a1, a2, a3, a_addr);
            ldsm_x2(b0, b1, b_addr);
            mma_bf16(c0, a0, a1, a2, a3, b0, b1);
            ldsm_x4(a0, a1, a2, a3, a_addr + 32);
            ldsm_x2(b0, b1, b_addr + 32);
            mma_bf16(c1, a0, a1, a2, a3, b0, b1);
            a_addr += 64; b_addr += 64;
        }
        #pragma unroll
        for (int q = 0; q < 4; q++) {
            const int rg = r0 + (lane >> 2) + 8 * (q >> 1);
            const int cg = n0 + 2 * (lane & 3) + (q & 1);
            const bool ok = (mb < 2 || rg >= 32) && (nb < 4 || cg >= 32);
            if (ok) s->G[rg * 36 + cg] = c0[q] + c1[q];
        }
    }
    __syncthreads();

    // ---- phase 3: distances + gaussian kernel row sums ----
    if (tid < NREG) s->invn[tid] = 1.0f / (sqrtf(s->G[tid * 36 + tid]) + 1e-8f);
    __syncthreads();
    for (int p = tid; p < NREG * NREG; p += 512) {
        const int i = p / 36, j = p - i * 36;
        const float e  = s->G[p] * s->invn[i] * s->invn[j];
        const float d2 = fmaxf(2.0f - 2.0f * e, 0.0f);
        s->G[p] = sqrtf(d2 + 1e-12f);
    }
    __syncthreads();
    if (tid < NKER * NREG) {
        const int k = tid / 36, i = tid - k * 36;
        const float m = s->mk[k], pr = s->pk[k];
        float acc = 0.f;
        #pragma unroll 6
        for (int j = 0; j < 36; j++) {
            const float t2 = s->G[i * 36 + j] - m;
            acc += fexp(-0.5f * pr * t2 * t2);
        }
        s->nf[tid] = acc / (acc + 1e-8f);
    }
    __syncthreads();

    // ---- phase 4: hidden (overlay hid/h1 on dead A region) ----
    float* hid = reinterpret_cast<float*>(s->A2);
    float* h1  = hid + NREG * HIDD;   // padded rows of 33 below
    for (int p = tid; p < NREG * HIDD; p += 512) {
        const int i = p >> 5, h = p & 31;
        float acc = 0.f;
        #pragma unroll
        for (int k = 0; k < NKER; k++) {
            const float c = s->nf[k * 36 + i];
            #pragma unroll
            for (int d = 0; d < SIMD; d++)
                acc = fmaf(c * s->sv[i * SIMD + d], s->gw[(k * SIMD + d) * HIDD + h], acc);
        }
        hid[p] = acc;
    }
    __syncthreads();

    // ---- phase 5: weight-normed MLP + mean ----
    for (int p = tid; p < NREG * HIDD; p += 512) {
        const int i = p >> 5, hh = p & 31;
        float acc = s->b1h[hh];
        #pragma unroll
        for (int h = 0; h < HIDD; h++)
            acc = fmaf(hid[i * HIDD + h], s->w1n[hh * 33 + h], acc);
        h1[i * 33 + hh] = tanhf(acc);
    }
    __syncthreads();
    if (tid < NREG) {
        float acc = s->b2s;
        #pragma unroll
        for (int h = 0; h < HIDD; h++)
            acc = fmaf(h1[tid * 33 + h], s->w2n[h], acc);
        s->sarr[tid] = acc;
    }
    __syncthreads();
    if (tid == 0) {
        float acc = 0.f;
        #pragma unroll
        for (int i = 0; i < NREG; i++) acc += s->sarr[i];
        out[b] = acc * (1.0f / 36.0f);
    }
}

extern "C" void kernel_launch(void* const* d_in, const int* in_sizes, int n_in,
                              void* d_out, int out_size) {
    const int Bn = in_sizes[0] / (NREG * EMBD);
    cudaFuncSetAttribute(simgsmn_kernel, cudaFuncAttributeMaxDynamicSharedMemorySize,
                         (int)sizeof(Smem));
    simgsmn_kernel<<<Bn, 512, sizeof(Smem)>>>(
        (const float*)d_in[0], (const float*)d_in[1], (const float*)d_in[2],
        (const float*)d_in[3], (const float*)d_in[4], (const float*)d_in[5],
        (const float*)d_in[6], (const float*)d_in[7], (const float*)d_in[8],
        (const float*)d_in[9], (const float*)d_in[10], (float*)d_out);
}

// round 3
// speedup vs baseline: 3.7111x; 1.9513x over previous
#include <cuda_runtime.h>
#include <math.h>

#define NREG 36
#define EMBD 1024
#define SIMD 16
#define HIDD 32
#define NKER 8

// Precomputed constants (written by prep_kernel, read by main kernel)
__device__ float g_gsum[SIMD * HIDD];   // sum over K of gcn_w  (16x32)
__device__ float g_w1n[HIDD * 33];      // weight-normed out1, padded rows
__device__ float g_w2n[HIDD];
__device__ float g_b1[HIDD];
__device__ float g_b2;

__global__ void prep_kernel(const float* __restrict__ gcn_w,
                            const float* __restrict__ out1_v, const float* __restrict__ out1_g,
                            const float* __restrict__ out1_b, const float* __restrict__ out2_v,
                            const float* __restrict__ out2_g, const float* __restrict__ out2_b)
{
    const int tid = threadIdx.x;  // 512 threads
    if (tid < SIMD * HIDD) {
        float a = 0.f;
        #pragma unroll
        for (int k = 0; k < NKER; k++) a += gcn_w[k * SIMD * HIDD + tid];
        g_gsum[tid] = a;
    }
    if (tid < HIDD) {
        float ss = 0.f;
        #pragma unroll
        for (int h = 0; h < HIDD; h++) { float v = out1_v[tid * HIDD + h]; ss += v * v; }
        const float sc = out1_g[tid] / (sqrtf(ss) + 1e-12f);
        #pragma unroll
        for (int h = 0; h < HIDD; h++) g_w1n[tid * 33 + h] = out1_v[tid * HIDD + h] * sc;
        g_b1[tid] = out1_b[tid];
    }
    if (tid == 32) {
        float ss = 0.f;
        #pragma unroll
        for (int h = 0; h < HIDD; h++) { float v = out2_v[h]; ss += v * v; }
        const float sc = out2_g[0] / (sqrtf(ss) + 1e-12f);
        #pragma unroll
        for (int h = 0; h < HIDD; h++) g_w2n[h] = out2_v[h] * sc;
        g_b2 = out2_b[0];
    }
}

struct SmemM {
    float sv[NREG * SIMD];
    float hid[NREG * HIDD];
    float h1[NREG * 33];      // padded
    float gsum[SIMD * HIDD];
    float w1n[HIDD * 33];
    float w2n[HIDD];
    float b1[HIDD];
    float sarr[NREG];
};

__global__ void __launch_bounds__(128, 8)
simgsmn_main(const float* __restrict__ inp1, const float* __restrict__ inp2,
             float* __restrict__ out)
{
    __shared__ SmemM s;
    const int tid  = threadIdx.x;
    const int w    = tid >> 5;
    const int lane = tid & 31;
    const int b    = blockIdx.x;

    // copy tiny constant tables to smem (L2-hot)
    for (int i = tid; i < SIMD * HIDD; i += 128) s.gsum[i] = g_gsum[i];
    for (int i = tid; i < HIDD * 33; i += 128)   s.w1n[i]  = g_w1n[i];
    if (tid < HIDD) { s.w2n[tid] = g_w2n[tid]; s.b1[tid] = g_b1[tid]; }

    // ---- stream inp1/inp2, compute block-cosine sim_vec ----
    // warp per row; lane's float4 at (step*32 + lane) covers sim-block 2*step + (lane>>4);
    // reduce q,c,x within 16-lane halves.
    const float4* in1 = reinterpret_cast<const float4*>(inp1) + (size_t)b * (NREG * EMBD / 4);
    const float4* in2 = reinterpret_cast<const float4*>(inp2) + (size_t)b * (NREG * EMBD / 4);
    #pragma unroll
    for (int ii = 0; ii < 9; ii++) {
        const int i = w + ii * 4;  // 4 warps, 9 rows each
        #pragma unroll
        for (int half = 0; half < 2; half++) {
            float4 av[4], cv[4];
            #pragma unroll
            for (int r = 0; r < 4; r++) {
                const int f4 = (half * 4 + r) * 32 + lane;
                av[r] = in1[i * 256 + f4];
                cv[r] = in2[i * 256 + f4];
            }
            #pragma unroll
            for (int r = 0; r < 4; r++) {
                float q = av[r].x * av[r].x + av[r].y * av[r].y + av[r].z * av[r].z + av[r].w * av[r].w;
                float c = cv[r].x * cv[r].x + cv[r].y * cv[r].y + cv[r].z * cv[r].z + cv[r].w * cv[r].w;
                float x = av[r].x * cv[r].x + av[r].y * cv[r].y + av[r].z * cv[r].z + av[r].w * cv[r].w;
                #pragma unroll
                for (int d = 1; d < 16; d <<= 1) {
                    q += __shfl_xor_sync(0xffffffffu, q, d);
                    c += __shfl_xor_sync(0xffffffffu, c, d);
                    x += __shfl_xor_sync(0xffffffffu, x, d);
                }
                if ((lane & 15) == 0) {
                    const int sb = (half * 4 + r) * 2 + (lane >> 4);
                    s.sv[i * SIMD + sb] = x / ((sqrtf(q) + 1e-8f) * (sqrtf(c) + 1e-8f));
                }
            }
        }
    }
    __syncthreads();

    // ---- hidden[i,h] = sum_d sv[i,d] * gsum[d,h]  (nf factor == 1 to <1e-6) ----
    for (int p = tid; p < NREG * HIDD; p += 128) {
        const int i = p >> 5, h = p & 31;
        float acc = 0.f;
        #pragma unroll
        for (int d = 0; d < SIMD; d++)
            acc = fmaf(s.sv[i * SIMD + d], s.gsum[d * HIDD + h], acc);
        s.hid[p] = acc;
    }
    __syncthreads();

    // ---- weight-normed MLP ----
    for (int p = tid; p < NREG * HIDD; p += 128) {
        const int i = p >> 5, hh = p & 31;
        float acc = s.b1[hh];
        #pragma unroll
        for (int h = 0; h < HIDD; h++)
            acc = fmaf(s.hid[i * HIDD + h], s.w1n[hh * 33 + h], acc);
        s.h1[i * 33 + hh] = tanhf(acc);
    }
    __syncthreads();
    if (tid < NREG) {
        float acc = g_b2;
        #pragma unroll
        for (int h = 0; h < HIDD; h++)
            acc = fmaf(s.h1[tid * 33 + h], s.w2n[h], acc);
        s.sarr[tid] = acc;
    }
    __syncthreads();
    if (tid == 0) {
        float acc = 0.f;
        #pragma unroll
        for (int i = 0; i < NREG; i++) acc += s.sarr[i];
        out[b] = acc * (1.0f / 36.0f);
    }
}

extern "C" void kernel_launch(void* const* d_in, const int* in_sizes, int n_in,
                              void* d_out, int out_size) {
    const int Bn = in_sizes[0] / (NREG * EMBD);
    prep_kernel<<<1, 512>>>((const float*)d_in[4], (const float*)d_in[5],
                            (const float*)d_in[6], (const float*)d_in[7],
                            (const float*)d_in[8], (const float*)d_in[9],
                            (const float*)d_in[10]);
    simgsmn_main<<<Bn, 128>>>((const float*)d_in[0], (const float*)d_in[1], (float*)d_out);
}

// round 4
// speedup vs baseline: 3.7121x; 1.0003x over previous
#include <cuda_runtime.h>
#include <math.h>

#define NREG 36
#define EMBD 1024
#define SIMD 16
#define HIDD 32
#define NKER 8

// Precomputed folded constants (prep_kernel -> main kernel)
__device__ float g_W1f[SIMD * HIDD];  // gsum · w1n^T folded: [d][hh]
__device__ float g_w2s[HIDD];         // weight-normed out2 row / 36
__device__ float g_b1[HIDD];
__device__ float g_b2;

__global__ void prep_kernel(const float* __restrict__ gcn_w,
                            const float* __restrict__ out1_v, const float* __restrict__ out1_g,
                            const float* __restrict__ out1_b, const float* __restrict__ out2_v,
                            const float* __restrict__ out2_g, const float* __restrict__ out2_b)
{
    __shared__ float gs[SIMD * HIDD];    // sum_k gcn_w [d][h]
    __shared__ float w1[HIDD * HIDD];    // weight-normed out1 [hh][h]
    const int tid = threadIdx.x;  // 512
    {
        float a = 0.f;
        #pragma unroll
        for (int k = 0; k < NKER; k++) a += gcn_w[k * SIMD * HIDD + tid];
        gs[tid] = a;
    }
    if (tid < HIDD) {
        float ss = 0.f;
        #pragma unroll
        for (int h = 0; h < HIDD; h++) { float v = out1_v[tid * HIDD + h]; ss += v * v; }
        const float sc = out1_g[tid] / (sqrtf(ss) + 1e-12f);
        #pragma unroll
        for (int h = 0; h < HIDD; h++) w1[tid * HIDD + h] = out1_v[tid * HIDD + h] * sc;
        g_b1[tid] = out1_b[tid];
    }
    if (tid == 32) {
        float ss = 0.f;
        #pragma unroll
        for (int h = 0; h < HIDD; h++) { float v = out2_v[h]; ss += v * v; }
        const float sc = out2_g[0] / (sqrtf(ss) + 1e-12f);
        #pragma unroll
        for (int h = 0; h < HIDD; h++) g_w2s[h] = out2_v[h] * sc * (1.0f / 36.0f);
        g_b2 = out2_b[0];
    }
    __syncthreads();
    // W1f[d][hh] = sum_h gs[d][h] * w1[hh][h]
    {
        const int d = tid >> 5, hh = tid & 31;
        float acc = 0.f;
        #pragma unroll
        for (int h = 0; h < HIDD; h++)
            acc = fmaf(gs[d * HIDD + h], w1[hh * HIDD + h], acc);
        g_W1f[d * HIDD + hh] = acc;
    }
}

__global__ void __launch_bounds__(128, 12)
simgsmn_main(const float* __restrict__ inp1, const float* __restrict__ inp2,
             float* __restrict__ out)
{
    __shared__ float sv[NREG * SIMD];
    __shared__ float W1fs[SIMD * HIDD];
    __shared__ float w2ss[HIDD];
    __shared__ float b1s[HIDD];
    __shared__ float red[4];
    const int tid  = threadIdx.x;
    const int w    = tid >> 5;
    const int lane = tid & 31;
    const int b    = blockIdx.x;

    #pragma unroll
    for (int r = 0; r < 4; r++) W1fs[tid + r * 128] = g_W1f[tid + r * 128];
    if (tid < HIDD) { w2ss[tid] = g_w2s[tid]; b1s[tid] = g_b1[tid]; }

    // ---- stream inp1/inp2, compute block-cosine sim_vec ----
    // warp per row; float4 index f4 = s*32+lane covers sim-block 2s + (lane>>4);
    // chunks of 2 steps (4 LDG.128 batched) keep regs under the 12-CTA cap.
    const float4* in1 = reinterpret_cast<const float4*>(inp1) + (size_t)b * (NREG * EMBD / 4);
    const float4* in2 = reinterpret_cast<const float4*>(inp2) + (size_t)b * (NREG * EMBD / 4);
    #pragma unroll
    for (int ii = 0; ii < 9; ii++) {
        const int i = w + ii * 4;
        const float4* p1 = in1 + i * 256;
        const float4* p2 = in2 + i * 256;
        #pragma unroll
        for (int ch = 0; ch < 4; ch++) {
            float4 a0 = p1[ch * 64 + lane];
            float4 c0 = p2[ch * 64 + lane];
            float4 a1 = p1[ch * 64 + 32 + lane];
            float4 c1 = p2[ch * 64 + 32 + lane];
            #pragma unroll
            for (int r = 0; r < 2; r++) {
                const float4 a = r ? a1 : a0;
                const float4 c = r ? c1 : c0;
                float q = a.x * a.x + a.y * a.y + a.z * a.z + a.w * a.w;
                float n = c.x * c.x + c.y * c.y + c.z * c.z + c.w * c.w;
                float x = a.x * c.x + a.y * c.y + a.z * c.z + a.w * c.w;
                #pragma unroll
                for (int d = 1; d < 16; d <<= 1) {
                    q += __shfl_xor_sync(0xffffffffu, q, d);
                    n += __shfl_xor_sync(0xffffffffu, n, d);
                    x += __shfl_xor_sync(0xffffffffu, x, d);
                }
                if ((lane & 15) == 0) {
                    const int sb = 4 * ch + 2 * r + (lane >> 4);
                    sv[i * SIMD + sb] = x / ((sqrtf(q) + 1e-8f) * (sqrtf(n) + 1e-8f));
                }
            }
        }
    }
    __syncthreads();

    // ---- fused tail: out = b2 + sum_{i,hh} w2s[hh] * tanh(b1[hh] + sum_d sv[i,d] W1f[d,hh]) ----
    float part = 0.f;
    #pragma unroll
    for (int q = 0; q < 9; q++) {
        const int p = tid + q * 128;
        const int i = p >> 5, hh = p & 31;
        float acc = b1s[hh];
        #pragma unroll
        for (int d = 0; d < SIMD; d++)
            acc = fmaf(sv[i * SIMD + d], W1fs[d * HIDD + hh], acc);
        part = fmaf(w2ss[hh], tanhf(acc), part);
    }
    #pragma unroll
    for (int d = 1; d < 32; d <<= 1)
        part += __shfl_xor_sync(0xffffffffu, part, d);
    if (lane == 0) red[w] = part;
    __syncthreads();
    if (tid == 0)
        out[b] = g_b2 + red[0] + red[1] + red[2] + red[3];
}

extern "C" void kernel_launch(void* const* d_in, const int* in_sizes, int n_in,
                              void* d_out, int out_size) {
    const int Bn = in_sizes[0] / (NREG * EMBD);
    prep_kernel<<<1, 512>>>((const float*)d_in[4], (const float*)d_in[5],
                            (const float*)d_in[6], (const float*)d_in[7],
                            (const float*)d_in[8], (const float*)d_in[9],
                            (const float*)d_in[10]);
    simgsmn_main<<<Bn, 128>>>((const float*)d_in[0], (const float*)d_in[1], (float*)d_out);
}

// round 5
// speedup vs baseline: 4.2677x; 1.1497x over previous
#include <cuda_runtime.h>
#include <math.h>

#define NREG 36
#define EMBD 1024
#define SIMD 16
#define HIDD 32
#define NKER 8

// Precomputed folded constants (prep_kernel -> main kernel)
__device__ float g_W1f[SIMD * HIDD];  // gsum · w1n^T folded: [d][hh]
__device__ float g_w2s[HIDD];         // weight-normed out2 row / 36
__device__ float g_b1[HIDD];
__device__ float g_b2;

__global__ void prep_kernel(const float* __restrict__ gcn_w,
                            const float* __restrict__ out1_v, const float* __restrict__ out1_g,
                            const float* __restrict__ out1_b, const float* __restrict__ out2_v,
                            const float* __restrict__ out2_g, const float* __restrict__ out2_b)
{
    __shared__ float gs[SIMD * HIDD];
    __shared__ float w1[HIDD * HIDD];
    const int tid = threadIdx.x;  // 512
    {
        float a = 0.f;
        #pragma unroll
        for (int k = 0; k < NKER; k++) a += gcn_w[k * SIMD * HIDD + tid];
        gs[tid] = a;
    }
    if (tid < HIDD) {
        float ss = 0.f;
        #pragma unroll
        for (int h = 0; h < HIDD; h++) { float v = out1_v[tid * HIDD + h]; ss += v * v; }
        const float sc = out1_g[tid] / (sqrtf(ss) + 1e-12f);
        #pragma unroll
        for (int h = 0; h < HIDD; h++) w1[tid * HIDD + h] = out1_v[tid * HIDD + h] * sc;
        g_b1[tid] = out1_b[tid];
    }
    if (tid == 32) {
        float ss = 0.f;
        #pragma unroll
        for (int h = 0; h < HIDD; h++) { float v = out2_v[h]; ss += v * v; }
        const float sc = out2_g[0] / (sqrtf(ss) + 1e-12f);
        #pragma unroll
        for (int h = 0; h < HIDD; h++) g_w2s[h] = out2_v[h] * sc * (1.0f / 36.0f);
        g_b2 = out2_b[0];
    }
    __syncthreads();
    {
        const int d = tid >> 5, hh = tid & 31;
        float acc = 0.f;
        #pragma unroll
        for (int h = 0; h < HIDD; h++)
            acc = fmaf(gs[d * HIDD + h], w1[hh * HIDD + h], acc);
        g_W1f[d * HIDD + hh] = acc;
    }
}

__device__ __forceinline__ void dot3(float& q, float& n, float& x, const float4 a, const float4 c) {
    q = fmaf(a.x, a.x, q); q = fmaf(a.y, a.y, q); q = fmaf(a.z, a.z, q); q = fmaf(a.w, a.w, q);
    n = fmaf(c.x, c.x, n); n = fmaf(c.y, c.y, n); n = fmaf(c.z, c.z, n); n = fmaf(c.w, c.w, n);
    x = fmaf(a.x, c.x, x); x = fmaf(a.y, c.y, x); x = fmaf(a.z, c.z, x); x = fmaf(a.w, c.w, x);
}

__global__ void __launch_bounds__(128, 9)
simgsmn_main(const float* __restrict__ inp1, const float* __restrict__ inp2,
             float* __restrict__ out)
{
    __shared__ float sv[NREG * SIMD];
    __shared__ float W1fs[SIMD * HIDD];
    __shared__ float w2ss[HIDD];
    __shared__ float b1s[HIDD];
    __shared__ float red[4];
    const int tid  = threadIdx.x;
    const int w    = tid >> 5;
    const int lane = tid & 31;
    const int g    = lane >> 2;   // 8 groups of 4 lanes; group g owns sim blocks 2g, 2g+1
    const int c4   = lane & 3;
    const int b    = blockIdx.x;

    #pragma unroll
    for (int r = 0; r < 4; r++) W1fs[tid + r * 128] = g_W1f[tid + r * 128];
    if (tid < HIDD) { w2ss[tid] = g_w2s[tid]; b1s[tid] = g_b1[tid]; }

    // ---- stream inp1/inp2, thread-local block-cosine accumulation ----
    // lane base within a row: float4 index g*32 + c4; steps s add 4s.
    // Depth-4 rotating pipeline: while computing steps 0-3 (block 2g), loads for
    // steps 4-7 are in flight; while computing 4-7 (block 2g+1), next row's
    // steps 0-3 are in flight. 4 LDG.128 pairs continuously outstanding.
    const float4* p1 = reinterpret_cast<const float4*>(inp1)
                     + (size_t)b * (NREG * EMBD / 4) + w * 256 + g * 32 + c4;
    const float4* p2 = reinterpret_cast<const float4*>(inp2)
                     + (size_t)b * (NREG * EMBD / 4) + w * 256 + g * 32 + c4;

    float4 A0 = __ldcs(p1 +  0), C0 = __ldcs(p2 +  0);
    float4 A1 = __ldcs(p1 +  4), C1 = __ldcs(p2 +  4);
    float4 A2 = __ldcs(p1 +  8), C2 = __ldcs(p2 +  8);
    float4 A3 = __ldcs(p1 + 12), C3 = __ldcs(p2 + 12);

    for (int ii = 0; ii < 9; ii++) {
        const int i = w + ii * 4;
        const float4* np1 = (ii < 8) ? (p1 + 1024) : p1;  // clamp: last iter reloads (discarded)
        const float4* np2 = (ii < 8) ? (p2 + 1024) : p2;
        float q0 = 0.f, n0 = 0.f, x0 = 0.f, q1 = 0.f, n1 = 0.f, x1 = 0.f;

        { float4 a = A0, c = C0; A0 = __ldcs(p1 + 16); C0 = __ldcs(p2 + 16); dot3(q0, n0, x0, a, c); }
        { float4 a = A1, c = C1; A1 = __ldcs(p1 + 20); C1 = __ldcs(p2 + 20); dot3(q0, n0, x0, a, c); }
        { float4 a = A2, c = C2; A2 = __ldcs(p1 + 24); C2 = __ldcs(p2 + 24); dot3(q0, n0, x0, a, c); }
        { float4 a = A3, c = C3; A3 = __ldcs(p1 + 28); C3 = __ldcs(p2 + 28); dot3(q0, n0, x0, a, c); }
        { float4 a = A0, c = C0; A0 = __ldcs(np1 +  0); C0 = __ldcs(np2 +  0); dot3(q1, n1, x1, a, c); }
        { float4 a = A1, c = C1; A1 = __ldcs(np1 +  4); C1 = __ldcs(np2 +  4); dot3(q1, n1, x1, a, c); }
        { float4 a = A2, c = C2; A2 = __ldcs(np1 +  8); C2 = __ldcs(np2 +  8); dot3(q1, n1, x1, a, c); }
        { float4 a = A3, c = C3; A3 = __ldcs(np1 + 12); C3 = __ldcs(np2 + 12); dot3(q1, n1, x1, a, c); }

        // reduce over the 4 lanes of the group (xor 1, 2 stay in-group)
        #pragma unroll
        for (int m = 1; m < 4; m <<= 1) {
            q0 += __shfl_xor_sync(0xffffffffu, q0, m);
            n0 += __shfl_xor_sync(0xffffffffu, n0, m);
            x0 += __shfl_xor_sync(0xffffffffu, x0, m);
            q1 += __shfl_xor_sync(0xffffffffu, q1, m);
            n1 += __shfl_xor_sync(0xffffffffu, n1, m);
            x1 += __shfl_xor_sync(0xffffffffu, x1, m);
        }
        if (c4 == 0) {
            sv[i * SIMD + 2 * g]     = x0 / ((sqrtf(q0) + 1e-8f) * (sqrtf(n0) + 1e-8f));
            sv[i * SIMD + 2 * g + 1] = x1 / ((sqrtf(q1) + 1e-8f) * (sqrtf(n1) + 1e-8f));
        }
        p1 = np1; p2 = np2;
    }
    __syncthreads();

    // ---- fused tail: out = b2 + sum_{i,hh} w2s[hh]*tanh(b1[hh] + sum_d sv[i,d]*W1f[d,hh]) ----
    float part = 0.f;
    #pragma unroll
    for (int q = 0; q < 9; q++) {
        const int p = tid + q * 128;
        const int i = p >> 5, hh = p & 31;
        float acc = b1s[hh];
        #pragma unroll
        for (int d = 0; d < SIMD; d++)
            acc = fmaf(sv[i * SIMD + d], W1fs[d * HIDD + hh], acc);
        part = fmaf(w2ss[hh], tanhf(acc), part);
    }
    #pragma unroll
    for (int d = 1; d < 32; d <<= 1)
        part += __shfl_xor_sync(0xffffffffu, part, d);
    if (lane == 0) red[w] = part;
    __syncthreads();
    if (tid == 0)
        out[b] = g_b2 + red[0] + red[1] + red[2] + red[3];
}

extern "C" void kernel_launch(void* const* d_in, const int* in_sizes, int n_in,
                              void* d_out, int out_size) {
    const int Bn = in_sizes[0] / (NREG * EMBD);
    prep_kernel<<<1, 512>>>((const float*)d_in[4], (const float*)d_in[5],
                            (const float*)d_in[6], (const float*)d_in[7],
                            (const float*)d_in[8], (const float*)d_in[9],
                            (const float*)d_in[10]);
    simgsmn_main<<<Bn, 128>>>((const float*)d_in[0], (const float*)d_in[1], (float*)d_out);
}